// round 5
// baseline (speedup 1.0000x reference)
#include <cuda_runtime.h>
#include <mma.h>
#include <cstdint>
#include <cstddef>

using namespace nvcuda;

// Problem constants (fixed by the reference)
#define NN 100000
#define EE 600000
#define DD 128
#define LL 5
#define BN_EPS 1e-5f
#define NPAD (NN + 128)   // pad so tail-block wmma stores stay in bounds

// ---------------------------------------------------------------------------
// Device scratch
// ---------------------------------------------------------------------------
__device__ __align__(16) float         g_hl[(size_t)NPAD * DD]; // post-linear features
__device__ __align__(16) float         g_hn[(size_t)NN * DD];   // layer output (pre-BN h)
__device__ __align__(16) unsigned char g_ea[(size_t)EE * DD];   // edge_attr u8, CSR order
__device__ __align__(16) int           g_srcn[EE];              // CSR: source node per slot
__device__ __align__(16) float         g_enorm[EE];             // CSR: norm per slot
__device__ __align__(16) int           g_pos[EE];               // edge e -> CSR slot
__device__ __align__(16) int           g_degcnt[NN];            // out-degree (by row)
__device__ __align__(16) int           g_indeg[NN];             // in-degree (by col)
__device__ __align__(16) int           g_cursor[NN];
__device__ __align__(16) int           g_off[NN + 1];           // CSR offsets (exclusive)
__device__ __align__(16) int           g_bsum[128];
__device__ __align__(16) float         g_invdeg[NN];
__device__ __align__(16) float         g_dinv[NN];
__device__ __align__(16) float         g_scl[LL * DD];          // gamma*rsqrt(var+eps)
__device__ __align__(16) float         g_sft[LL * DD];          // beta - mean*scale
__device__ int g_is64;

// cvt.rna.tf32.f32 needs a .b32 destination register -> "=r" operand
__device__ __forceinline__ float to_tf32(float x) {
    uint32_t r;
    asm("cvt.rna.tf32.f32 %0, %1;" : "=r"(r) : "f"(x));
    return __uint_as_float(r);
}

// ---------------------------------------------------------------------------
// Preprocessing
// ---------------------------------------------------------------------------
// Detect int64 vs int32 edge_index: if int64 with values < 2^17, every odd
// 32-bit word is zero. Reading 8192 ints is in-bounds either way.
__global__ void k_detect(const int* __restrict__ ei32) {
    __shared__ int s_any;
    if (threadIdx.x == 0) s_any = 0;
    __syncthreads();
    int v = 0;
    for (int i = threadIdx.x; i < 4096; i += blockDim.x)
        v |= ei32[2 * i + 1];
    atomicOr(&s_any, v);
    __syncthreads();
    if (threadIdx.x == 0) g_is64 = (s_any == 0) ? 1 : 0;
}

__global__ void k_zero() {
    int i = blockIdx.x * blockDim.x + threadIdx.x;
    if (i < NN) { g_degcnt[i] = 0; g_indeg[i] = 0; g_cursor[i] = 0; }
}

__device__ __forceinline__ void load_edge(const void* ei, int e, int& r, int& c) {
    if (g_is64) {
        const long long* p = (const long long*)ei;
        r = (int)p[e]; c = (int)p[EE + e];
    } else {
        const int* p = (const int*)ei;
        r = p[e]; c = p[EE + e];
    }
    r = min(max(r, 0), NN - 1);
    c = min(max(c, 0), NN - 1);
}

__global__ void k_edge_pre(const void* __restrict__ ei) {
    int e = blockIdx.x * blockDim.x + threadIdx.x;
    if (e >= EE) return;
    int r, c; load_edge(ei, e, r, c);
    atomicAdd(&g_degcnt[r], 1);
    atomicAdd(&g_indeg[c], 1);
}

__global__ void k_node() {
    int n = blockIdx.x * blockDim.x + threadIdx.x;
    if (n >= NN) return;
    float d = (float)(g_degcnt[n] + 1);
    g_invdeg[n] = 1.0f / d;
    g_dinv[n]   = rsqrtf(d);
}

// Block-level exclusive scan of g_indeg into g_off (3-phase)
__global__ void k_scan1() {            // grid 98, block 1024
    __shared__ int s[1024];
    int i = blockIdx.x * 1024 + threadIdx.x;
    int v = (i < NN) ? g_indeg[i] : 0;
    s[threadIdx.x] = v;
    __syncthreads();
    for (int d = 1; d < 1024; d <<= 1) {
        int t = (threadIdx.x >= d) ? s[threadIdx.x - d] : 0;
        __syncthreads();
        s[threadIdx.x] += t;
        __syncthreads();
    }
    if (i < NN) g_off[i] = s[threadIdx.x] - v;     // exclusive within block
    if (threadIdx.x == 1023) g_bsum[blockIdx.x] = s[1023];
}

__global__ void k_scan2() {            // 1 block, 128 threads
    __shared__ int s[128];
    int t = threadIdx.x;
    s[t] = (t < 98) ? g_bsum[t] : 0;
    __syncthreads();
    for (int d = 1; d < 128; d <<= 1) {
        int v = (t >= d) ? s[t - d] : 0;
        __syncthreads();
        s[t] += v;
        __syncthreads();
    }
    if (t < 98) g_bsum[t] = s[t];                  // inclusive
}

__global__ void k_scan3() {            // grid 98, block 1024
    int i = blockIdx.x * 1024 + threadIdx.x;
    int add = (blockIdx.x > 0) ? g_bsum[blockIdx.x - 1] : 0;
    if (i < NN) g_off[i] += add;
    if (i == NN) g_off[NN] = EE;
}

__global__ void k_place(const void* __restrict__ ei) {
    int e = blockIdx.x * blockDim.x + threadIdx.x;
    if (e >= EE) return;
    int r, c; load_edge(ei, e, r, c);
    int pos = g_off[c] + atomicAdd(&g_cursor[c], 1);
    g_srcn[pos]  = r;
    g_enorm[pos] = g_dinv[r] * g_dinv[c];
    g_pos[e]     = pos;
}

// Pack int32 edge_attr (values 0..3) -> u8 at the edge's CSR slot
__global__ void k_pack(const int4* __restrict__ ea) {
    int i = blockIdx.x * blockDim.x + threadIdx.x;   // chunk = 4 features
    if (i >= EE * 32) return;
    int e = i >> 5, j = i & 31;
    int4 v = __ldg(&ea[i]);
    unsigned int u = ((unsigned)v.x & 0xffu)
                   | (((unsigned)v.y & 0xffu) << 8)
                   | (((unsigned)v.z & 0xffu) << 16)
                   | (((unsigned)v.w & 0xffu) << 24);
    ((unsigned int*)g_ea)[(size_t)g_pos[e] * 32 + j] = u;
}

__global__ void k_bnconst(const float* __restrict__ gamma, const float* __restrict__ beta,
                          const float* __restrict__ mean,  const float* __restrict__ var) {
    int i = blockIdx.x * blockDim.x + threadIdx.x;
    if (i >= LL * DD) return;
    float s = gamma[i] * rsqrtf(var[i] + BN_EPS);
    g_scl[i] = s;
    g_sft[i] = beta[i] - mean[i] * s;
}

// ---------------------------------------------------------------------------
// Tensor-core GEMM (tf32x3): g_hl = affine_relu(A) @ W^T + bias
//   Bias folded as augmented K-column (A[:,128]=1, W[:,128]=bias), K_eff=144.
//   Block 128x128, 512 threads (16 warps, each 32x32 via 2x2 m16n16k8 tiles).
// ---------------------------------------------------------------------------
__global__ __launch_bounds__(512)
void k_gemm_tc(const float* __restrict__ A_in, const float* __restrict__ W,
               const float* __restrict__ bias, int aff)
{
    __shared__ float sAh[128][16], sAl[128][16];
    __shared__ float sBh[128][16], sBl[128][16];
    __shared__ float sScl[DD], sSft[DD];

    const float* A = A_in ? A_in : g_hn;

    int tid = threadIdx.x;
    int wid = tid >> 5;
    int wm = wid & 3;          // 4 m-chunks of 32
    int wn = wid >> 2;         // 4 n-chunks of 32
    int rowbase = blockIdx.x * 128;

    if (aff >= 0 && tid < DD) {
        sScl[tid] = g_scl[aff + tid];
        sSft[tid] = g_sft[aff + tid];
    }
    __syncthreads();

    int lrow = tid >> 2;            // 0..127
    int cg   = (tid & 3) * 4;       // 0,4,8,12
    int arow = rowbase + lrow;
    if (arow >= NN) arow = NN - 1;  // clamp (tail block loads only)
    const float* Ar = A + (size_t)arow * DD;
    const float* Wr = W + (size_t)lrow * DD;
    float biasv = __ldg(&bias[lrow]);

    wmma::fragment<wmma::accumulator, 16, 16, 8, float> acc[2][2];
    #pragma unroll
    for (int i = 0; i < 2; i++)
        #pragma unroll
        for (int j = 0; j < 2; j++) wmma::fill_fragment(acc[i][j], 0.0f);

    for (int s = 0; s < 9; ++s) {
        int k0 = s * 16;
        float av[4], bv[4];
        if (k0 < 128) {
            float4 a4 = __ldg((const float4*)(Ar + k0 + cg));
            float4 b4 = __ldg((const float4*)(Wr + k0 + cg));
            av[0] = a4.x; av[1] = a4.y; av[2] = a4.z; av[3] = a4.w;
            bv[0] = b4.x; bv[1] = b4.y; bv[2] = b4.z; bv[3] = b4.w;
            if (aff >= 0) {
                #pragma unroll
                for (int c = 0; c < 4; c++) {
                    int k = k0 + cg + c;
                    av[c] = fmaxf(fmaf(av[c], sScl[k], sSft[k]), 0.f);
                }
            }
        } else {
            #pragma unroll
            for (int c = 0; c < 4; c++) {
                int k = k0 + cg + c;
                av[c] = (k == 128) ? 1.0f : 0.0f;
                bv[c] = (k == 128) ? biasv : 0.0f;
            }
        }
        __syncthreads();   // previous step's compute done before overwrite
        #pragma unroll
        for (int c = 0; c < 4; c++) {
            float ah = to_tf32(av[c]);
            sAh[lrow][cg + c] = ah;
            sAl[lrow][cg + c] = to_tf32(av[c] - ah);
            float bh = to_tf32(bv[c]);
            sBh[lrow][cg + c] = bh;
            sBl[lrow][cg + c] = to_tf32(bv[c] - bh);
        }
        __syncthreads();

        #pragma unroll
        for (int ks = 0; ks < 16; ks += 8) {
            wmma::fragment<wmma::matrix_a, 16, 16, 8, wmma::precision::tf32, wmma::row_major> fah[2], fal[2];
            wmma::fragment<wmma::matrix_b, 16, 16, 8, wmma::precision::tf32, wmma::col_major> fbh[2], fbl[2];
            #pragma unroll
            for (int i = 0; i < 2; i++) {
                wmma::load_matrix_sync(fah[i], &sAh[wm * 32 + i * 16][ks], 16);
                wmma::load_matrix_sync(fal[i], &sAl[wm * 32 + i * 16][ks], 16);
            }
            #pragma unroll
            for (int j = 0; j < 2; j++) {
                wmma::load_matrix_sync(fbh[j], &sBh[wn * 32 + j * 16][ks], 16);
                wmma::load_matrix_sync(fbl[j], &sBl[wn * 32 + j * 16][ks], 16);
            }
            #pragma unroll
            for (int i = 0; i < 2; i++)
                #pragma unroll
                for (int j = 0; j < 2; j++) {
                    wmma::mma_sync(acc[i][j], fah[i], fbh[j], acc[i][j]);
                    wmma::mma_sync(acc[i][j], fah[i], fbl[j], acc[i][j]);
                    wmma::mma_sync(acc[i][j], fal[i], fbh[j], acc[i][j]);
                }
        }
    }

    // Store hl (g_hl is padded: tail-block rows land in padding)
    #pragma unroll
    for (int i = 0; i < 2; i++)
        #pragma unroll
        for (int j = 0; j < 2; j++) {
            float* p = g_hl + (size_t)(rowbase + wm * 32 + i * 16) * DD + wn * 32 + j * 16;
            wmma::store_matrix_sync(p, acc[i][j], DD, wmma::mem_row_major);
        }
}

// ---------------------------------------------------------------------------
// CSR aggregation: one warp per target node, no atomics.
//   acc = sum_{j in in(n)} norm_j * relu(hl[src_j] + attr_j)
//   acc += relu(hl[n] + root) * invdeg[n]
//   bnoff >= 0: apply BN, write to out; else write raw to g_hn
// ---------------------------------------------------------------------------
__global__ __launch_bounds__(256)
void k_edge_csr(const float* __restrict__ root, float* __restrict__ outp, int bnoff)
{
    int warp = (blockIdx.x * blockDim.x + threadIdx.x) >> 5;
    int lane = threadIdx.x & 31;
    if (warp >= NN) return;
    int n = warp;

    int beg = __ldg(&g_off[n]);
    int end = __ldg(&g_off[n + 1]);

    const float4* hl4 = (const float4*)g_hl;
    const unsigned int* ea4 = (const unsigned int*)g_ea;

    float4 acc = make_float4(0.f, 0.f, 0.f, 0.f);
    for (int j = beg; j < end; ++j) {
        int   src = __ldg(&g_srcn[j]);
        float nrm = __ldg(&g_enorm[j]);
        float4 h  = __ldg(hl4 + (size_t)src * 32 + lane);
        unsigned int u = __ldg(ea4 + (size_t)j * 32 + lane);
        acc.x += fmaxf(h.x + (float)( u        & 0xffu), 0.f) * nrm;
        acc.y += fmaxf(h.y + (float)((u >>  8) & 0xffu), 0.f) * nrm;
        acc.z += fmaxf(h.z + (float)((u >> 16) & 0xffu), 0.f) * nrm;
        acc.w += fmaxf(h.w + (float)((u >> 24) & 0xffu), 0.f) * nrm;
    }

    // self-loop term
    float4 hs = __ldg(hl4 + (size_t)n * 32 + lane);
    float4 rt = __ldg((const float4*)root + lane);
    float  id = __ldg(&g_invdeg[n]);
    acc.x += fmaxf(hs.x + rt.x, 0.f) * id;
    acc.y += fmaxf(hs.y + rt.y, 0.f) * id;
    acc.z += fmaxf(hs.z + rt.z, 0.f) * id;
    acc.w += fmaxf(hs.w + rt.w, 0.f) * id;

    if (bnoff >= 0) {   // last layer: BN (no relu) -> out
        float4 sc = *(const float4*)&g_scl[bnoff + lane * 4];
        float4 sf = *(const float4*)&g_sft[bnoff + lane * 4];
        acc.x = fmaf(acc.x, sc.x, sf.x);
        acc.y = fmaf(acc.y, sc.y, sf.y);
        acc.z = fmaf(acc.z, sc.z, sf.z);
        acc.w = fmaf(acc.w, sc.w, sf.w);
        ((float4*)outp)[(size_t)n * 32 + lane] = acc;
    } else {
        ((float4*)g_hn)[(size_t)n * 32 + lane] = acc;
    }
}

// ---------------------------------------------------------------------------
// Host driver (graph-capturable)
// ---------------------------------------------------------------------------
extern "C" void kernel_launch(void* const* d_in, const int* in_sizes, int n_in,
                              void* d_out, int out_size)
{
    const float* x     = (const float*)d_in[0];
    const void*  ei    = d_in[1];                 // dtype detected on device
    const int*   ea    = (const int*)d_in[2];
    const float* W     = (const float*)d_in[3];
    const float* b     = (const float*)d_in[4];
    const float* root  = (const float*)d_in[5];
    const float* gamma = (const float*)d_in[6];
    const float* beta  = (const float*)d_in[7];
    const float* mean  = (const float*)d_in[8];
    const float* var   = (const float*)d_in[9];
    (void)in_sizes; (void)n_in; (void)out_size;

    k_detect<<<1, 256>>>((const int*)ei);
    k_zero<<<(NN + 255) / 256, 256>>>();
    k_edge_pre<<<(EE + 255) / 256, 256>>>(ei);
    k_node<<<(NN + 255) / 256, 256>>>();
    k_scan1<<<98, 1024>>>();
    k_scan2<<<1, 128>>>();
    k_scan3<<<98, 1024>>>();
    k_place<<<(EE + 255) / 256, 256>>>(ei);
    k_pack<<<(EE * 32 + 255) / 256, 256>>>((const int4*)ea);
    k_bnconst<<<(LL * DD + 255) / 256, 256>>>(gamma, beta, mean, var);

    const int gemm_blocks = (NN + 127) / 128;     // 782
    const int edge_blocks = (NN + 7) / 8;         // 12500 (8 node-warps/block)

    for (int l = 0; l < LL; ++l) {
        const float* A   = (l == 0) ? x : nullptr;       // nullptr -> g_hn
        int          aff = (l == 0) ? -1 : (l - 1) * DD; // fold prev BN+relu
        k_gemm_tc<<<gemm_blocks, 512>>>(A, W + (size_t)l * DD * DD,
                                        b + (size_t)l * DD, aff);
        float* outp = (l == LL - 1) ? (float*)d_out : nullptr;
        int    bn   = (l == LL - 1) ? (LL - 1) * DD : -1;
        k_edge_csr<<<edge_blocks, 256>>>(root + (size_t)l * DD, outp, bn);
    }
}

// round 6
// speedup vs baseline: 1.7015x; 1.7015x over previous
#include <cuda_runtime.h>
#include <cstdint>
#include <cstddef>

// Problem constants (fixed by the reference)
#define NN 100000
#define EE 600000
#define DD 128
#define LL 5
#define BN_EPS 1e-5f

// ---------------------------------------------------------------------------
// Device scratch
// ---------------------------------------------------------------------------
__device__ __align__(16) float         g_hl[(size_t)NN * DD];   // post-linear features
__device__ __align__(16) float         g_hn[(size_t)NN * DD];   // layer output (pre-BN h)
__device__ __align__(16) unsigned char g_ea[(size_t)EE * DD];   // edge_attr u8, CSR order
__device__ __align__(16) int           g_srcn[EE];              // CSR: source node per slot
__device__ __align__(16) float         g_enorm[EE];             // CSR: norm per slot
__device__ __align__(16) int           g_pos[EE];               // edge e -> CSR slot
__device__ __align__(16) int           g_degcnt[NN];            // out-degree (by row)
__device__ __align__(16) int           g_indeg[NN];             // in-degree (by col)
__device__ __align__(16) int           g_cursor[NN];
__device__ __align__(16) int           g_off[NN + 1];           // CSR offsets (exclusive)
__device__ __align__(16) int           g_bsum[128];
__device__ __align__(16) float         g_invdeg[NN];
__device__ __align__(16) float         g_dinv[NN];
__device__ __align__(16) float         g_scl[LL * DD];          // gamma*rsqrt(var+eps)
__device__ __align__(16) float         g_sft[LL * DD];          // beta - mean*scale
__device__ int g_is64;

// ---------------------------------------------------------------------------
// Preprocessing
// ---------------------------------------------------------------------------
__global__ void k_detect(const int* __restrict__ ei32) {
    __shared__ int s_any;
    if (threadIdx.x == 0) s_any = 0;
    __syncthreads();
    int v = 0;
    for (int i = threadIdx.x; i < 4096; i += blockDim.x)
        v |= ei32[2 * i + 1];
    atomicOr(&s_any, v);
    __syncthreads();
    if (threadIdx.x == 0) g_is64 = (s_any == 0) ? 1 : 0;
}

__global__ void k_zero() {
    int i = blockIdx.x * blockDim.x + threadIdx.x;
    if (i < NN) { g_degcnt[i] = 0; g_indeg[i] = 0; g_cursor[i] = 0; }
}

__device__ __forceinline__ void load_edge(const void* ei, int e, int& r, int& c) {
    if (g_is64) {
        const long long* p = (const long long*)ei;
        r = (int)p[e]; c = (int)p[EE + e];
    } else {
        const int* p = (const int*)ei;
        r = p[e]; c = p[EE + e];
    }
    r = min(max(r, 0), NN - 1);
    c = min(max(c, 0), NN - 1);
}

__global__ void k_edge_pre(const void* __restrict__ ei) {
    int e = blockIdx.x * blockDim.x + threadIdx.x;
    if (e >= EE) return;
    int r, c; load_edge(ei, e, r, c);
    atomicAdd(&g_degcnt[r], 1);
    atomicAdd(&g_indeg[c], 1);
}

__global__ void k_node() {
    int n = blockIdx.x * blockDim.x + threadIdx.x;
    if (n >= NN) return;
    float d = (float)(g_degcnt[n] + 1);
    g_invdeg[n] = 1.0f / d;
    g_dinv[n]   = rsqrtf(d);
}

// Block-level exclusive scan of g_indeg into g_off (3-phase)
__global__ void k_scan1() {            // grid 98, block 1024
    __shared__ int s[1024];
    int i = blockIdx.x * 1024 + threadIdx.x;
    int v = (i < NN) ? g_indeg[i] : 0;
    s[threadIdx.x] = v;
    __syncthreads();
    for (int d = 1; d < 1024; d <<= 1) {
        int t = (threadIdx.x >= d) ? s[threadIdx.x - d] : 0;
        __syncthreads();
        s[threadIdx.x] += t;
        __syncthreads();
    }
    if (i < NN) g_off[i] = s[threadIdx.x] - v;     // exclusive within block
    if (threadIdx.x == 1023) g_bsum[blockIdx.x] = s[1023];
}

__global__ void k_scan2() {            // 1 block, 128 threads
    __shared__ int s[128];
    int t = threadIdx.x;
    s[t] = (t < 98) ? g_bsum[t] : 0;
    __syncthreads();
    for (int d = 1; d < 128; d <<= 1) {
        int v = (t >= d) ? s[t - d] : 0;
        __syncthreads();
        s[t] += v;
        __syncthreads();
    }
    if (t < 98) g_bsum[t] = s[t];                  // inclusive
}

__global__ void k_scan3() {            // grid 98, block 1024
    int i = blockIdx.x * 1024 + threadIdx.x;
    int add = (blockIdx.x > 0) ? g_bsum[blockIdx.x - 1] : 0;
    if (i < NN) g_off[i] += add;
    if (i == NN) g_off[NN] = EE;
}

__global__ void k_place(const void* __restrict__ ei) {
    int e = blockIdx.x * blockDim.x + threadIdx.x;
    if (e >= EE) return;
    int r, c; load_edge(ei, e, r, c);
    int pos = g_off[c] + atomicAdd(&g_cursor[c], 1);
    g_srcn[pos]  = r;
    g_enorm[pos] = g_dinv[r] * g_dinv[c];
    g_pos[e]     = pos;
}

// Pack int32 edge_attr (values 0..3) -> u8 at the edge's CSR slot
__global__ void k_pack(const int4* __restrict__ ea) {
    int i = blockIdx.x * blockDim.x + threadIdx.x;   // chunk = 4 features
    if (i >= EE * 32) return;
    int e = i >> 5, j = i & 31;
    int4 v = __ldg(&ea[i]);
    unsigned int u = ((unsigned)v.x & 0xffu)
                   | (((unsigned)v.y & 0xffu) << 8)
                   | (((unsigned)v.z & 0xffu) << 16)
                   | (((unsigned)v.w & 0xffu) << 24);
    ((unsigned int*)g_ea)[(size_t)g_pos[e] * 32 + j] = u;
}

__global__ void k_bnconst(const float* __restrict__ gamma, const float* __restrict__ beta,
                          const float* __restrict__ mean,  const float* __restrict__ var) {
    int i = blockIdx.x * blockDim.x + threadIdx.x;
    if (i >= LL * DD) return;
    float s = gamma[i] * rsqrtf(var[i] + BN_EPS);
    g_scl[i] = s;
    g_sft[i] = beta[i] - mean[i] * s;
}

// ---------------------------------------------------------------------------
// SIMT GEMM (proven in R3): g_hl = affine_relu(A) @ W^T + bias
//   A   : x for layer 0, else g_hn (pass nullptr)
//   aff : -1 identity, else offset into g_scl/g_sft (fold prev BN+relu)
// 128x128 tile, 256 threads, 8x8 per thread, BK=8. Writes ONLY g_hl.
// ---------------------------------------------------------------------------
__global__ __launch_bounds__(256)
void k_gemm(const float* __restrict__ A_in, const float* __restrict__ W,
            const float* __restrict__ bias, int aff)
{
    __shared__ float As[8][132];
    __shared__ float Bs[8][132];
    __shared__ float s_scl[DD];
    __shared__ float s_sft[DD];

    const float* A = A_in ? A_in : g_hn;

    int tid = threadIdx.x;
    int tx  = tid & 15;        // col group
    int ty  = tid >> 4;        // row group
    int rowbase = blockIdx.x * 128;

    if (aff >= 0 && tid < DD) {
        s_scl[tid] = g_scl[aff + tid];
        s_sft[tid] = g_sft[aff + tid];
    }
    __syncthreads();

    int lm = tid >> 1;          // 0..127 : A row / W row (output feature)
    int lk = (tid & 1) * 4;     // 0 or 4 : k sub-offset

    int arow = rowbase + lm;
    if (arow >= NN) arow = NN - 1;                     // clamp (tail block only)
    const float4* Arow4 = (const float4*)(A + (size_t)arow * DD);
    const float4* Wrow4 = (const float4*)(W + (size_t)lm * DD);

    float acc[8][8];
    #pragma unroll
    for (int i = 0; i < 8; i++)
        #pragma unroll
        for (int j = 0; j < 8; j++) acc[i][j] = 0.f;

    for (int kt = 0; kt < 16; ++kt) {
        float4 av = __ldg(&Arow4[kt * 2 + (tid & 1)]);
        if (aff >= 0) {
            int kb = kt * 8 + lk;
            av.x = fmaxf(fmaf(av.x, s_scl[kb + 0], s_sft[kb + 0]), 0.f);
            av.y = fmaxf(fmaf(av.y, s_scl[kb + 1], s_sft[kb + 1]), 0.f);
            av.z = fmaxf(fmaf(av.z, s_scl[kb + 2], s_sft[kb + 2]), 0.f);
            av.w = fmaxf(fmaf(av.w, s_scl[kb + 3], s_sft[kb + 3]), 0.f);
        }
        float4 wv = __ldg(&Wrow4[kt * 2 + (tid & 1)]);

        __syncthreads();
        As[lk + 0][lm] = av.x; As[lk + 1][lm] = av.y;
        As[lk + 2][lm] = av.z; As[lk + 3][lm] = av.w;
        Bs[lk + 0][lm] = wv.x; Bs[lk + 1][lm] = wv.y;
        Bs[lk + 2][lm] = wv.z; Bs[lk + 3][lm] = wv.w;
        __syncthreads();

        #pragma unroll
        for (int kk = 0; kk < 8; ++kk) {
            float a[8], bb[8];
            *(float4*)&a[0]  = *(const float4*)&As[kk][ty * 8];
            *(float4*)&a[4]  = *(const float4*)&As[kk][ty * 8 + 4];
            *(float4*)&bb[0] = *(const float4*)&Bs[kk][tx * 8];
            *(float4*)&bb[4] = *(const float4*)&Bs[kk][tx * 8 + 4];
            #pragma unroll
            for (int i = 0; i < 8; i++)
                #pragma unroll
                for (int j = 0; j < 8; j++)
                    acc[i][j] = fmaf(a[i], bb[j], acc[i][j]);
        }
    }

    float bias_r[8];
    *(float4*)&bias_r[0] = __ldg((const float4*)&bias[tx * 8]);
    *(float4*)&bias_r[4] = __ldg((const float4*)&bias[tx * 8 + 4]);

    #pragma unroll
    for (int i = 0; i < 8; i++) {
        int r = rowbase + ty * 8 + i;
        if (r >= NN) continue;
        float hv[8];
        #pragma unroll
        for (int j = 0; j < 8; j++) hv[j] = acc[i][j] + bias_r[j];
        float* hlp = g_hl + (size_t)r * DD + tx * 8;
        *(float4*)&hlp[0] = *(float4*)&hv[0];
        *(float4*)&hlp[4] = *(float4*)&hv[4];
    }
}

// ---------------------------------------------------------------------------
// CSR aggregation: one warp per target node, no atomics, 2-deep pipeline.
//   acc = sum_j norm_j * relu(hl[src_j] + attr_j) + relu(hl[n]+root)*invdeg
//   bnoff >= 0: apply BN (no relu), write to outp; else write raw to g_hn
// ---------------------------------------------------------------------------
__device__ __forceinline__ void acc_edge(float4& acc, float4 h, unsigned int u, float nrm) {
    acc.x += fmaxf(h.x + (float)( u        & 0xffu), 0.f) * nrm;
    acc.y += fmaxf(h.y + (float)((u >>  8) & 0xffu), 0.f) * nrm;
    acc.z += fmaxf(h.z + (float)((u >> 16) & 0xffu), 0.f) * nrm;
    acc.w += fmaxf(h.w + (float)((u >> 24) & 0xffu), 0.f) * nrm;
}

__global__ __launch_bounds__(256)
void k_edge_csr(const float* __restrict__ root, float* __restrict__ outp, int bnoff)
{
    int warp = (blockIdx.x * blockDim.x + threadIdx.x) >> 5;
    int lane = threadIdx.x & 31;
    if (warp >= NN) return;
    int n = warp;

    int beg = __ldg(&g_off[n]);
    int end = __ldg(&g_off[n + 1]);

    const float4* hl4 = (const float4*)g_hl;
    const unsigned int* ea4 = (const unsigned int*)g_ea;

    float4 acc = make_float4(0.f, 0.f, 0.f, 0.f);

    int j = beg;
    // 2-deep software pipeline: issue both gathers before consuming either
    for (; j + 1 < end; j += 2) {
        int   s0 = __ldg(&g_srcn[j]);
        int   s1 = __ldg(&g_srcn[j + 1]);
        float n0 = __ldg(&g_enorm[j]);
        float n1 = __ldg(&g_enorm[j + 1]);
        float4 h0 = __ldg(hl4 + (size_t)s0 * 32 + lane);
        float4 h1 = __ldg(hl4 + (size_t)s1 * 32 + lane);
        unsigned int u0 = __ldg(ea4 + (size_t)j * 32 + lane);
        unsigned int u1 = __ldg(ea4 + (size_t)(j + 1) * 32 + lane);
        acc_edge(acc, h0, u0, n0);
        acc_edge(acc, h1, u1, n1);
    }
    if (j < end) {
        int   s0 = __ldg(&g_srcn[j]);
        float n0 = __ldg(&g_enorm[j]);
        float4 h0 = __ldg(hl4 + (size_t)s0 * 32 + lane);
        unsigned int u0 = __ldg(ea4 + (size_t)j * 32 + lane);
        acc_edge(acc, h0, u0, n0);
    }

    // self-loop term
    float4 hs = __ldg(hl4 + (size_t)n * 32 + lane);
    float4 rt = __ldg((const float4*)root + lane);
    float  id = __ldg(&g_invdeg[n]);
    acc.x += fmaxf(hs.x + rt.x, 0.f) * id;
    acc.y += fmaxf(hs.y + rt.y, 0.f) * id;
    acc.z += fmaxf(hs.z + rt.z, 0.f) * id;
    acc.w += fmaxf(hs.w + rt.w, 0.f) * id;

    if (bnoff >= 0) {   // last layer: BN (no relu) -> out
        float4 sc = *(const float4*)&g_scl[bnoff + lane * 4];
        float4 sf = *(const float4*)&g_sft[bnoff + lane * 4];
        acc.x = fmaf(acc.x, sc.x, sf.x);
        acc.y = fmaf(acc.y, sc.y, sf.y);
        acc.z = fmaf(acc.z, sc.z, sf.z);
        acc.w = fmaf(acc.w, sc.w, sf.w);
        ((float4*)outp)[(size_t)n * 32 + lane] = acc;
    } else {
        ((float4*)g_hn)[(size_t)n * 32 + lane] = acc;
    }
}

// ---------------------------------------------------------------------------
// Host driver (graph-capturable)
// ---------------------------------------------------------------------------
extern "C" void kernel_launch(void* const* d_in, const int* in_sizes, int n_in,
                              void* d_out, int out_size)
{
    const float* x     = (const float*)d_in[0];
    const void*  ei    = d_in[1];                 // dtype detected on device
    const int*   ea    = (const int*)d_in[2];
    const float* W     = (const float*)d_in[3];
    const float* b     = (const float*)d_in[4];
    const float* root  = (const float*)d_in[5];
    const float* gamma = (const float*)d_in[6];
    const float* beta  = (const float*)d_in[7];
    const float* mean  = (const float*)d_in[8];
    const float* var   = (const float*)d_in[9];
    (void)in_sizes; (void)n_in; (void)out_size;

    k_detect<<<1, 256>>>((const int*)ei);
    k_zero<<<(NN + 255) / 256, 256>>>();
    k_edge_pre<<<(EE + 255) / 256, 256>>>(ei);
    k_node<<<(NN + 255) / 256, 256>>>();
    k_scan1<<<98, 1024>>>();
    k_scan2<<<1, 128>>>();
    k_scan3<<<98, 1024>>>();
    k_place<<<(EE + 255) / 256, 256>>>(ei);
    k_pack<<<(EE * 32 + 255) / 256, 256>>>((const int4*)ea);
    k_bnconst<<<(LL * DD + 255) / 256, 256>>>(gamma, beta, mean, var);

    const int gemm_blocks = (NN + 127) / 128;     // 782
    const int edge_blocks = (NN + 7) / 8;         // 12500 (8 node-warps/block)

    for (int l = 0; l < LL; ++l) {
        const float* A   = (l == 0) ? x : nullptr;       // nullptr -> g_hn
        int          aff = (l == 0) ? -1 : (l - 1) * DD; // fold prev BN+relu
        k_gemm<<<gemm_blocks, 256>>>(A, W + (size_t)l * DD * DD,
                                     b + (size_t)l * DD, aff);
        float* outp = (l == LL - 1) ? (float*)d_out : nullptr;
        int    bn   = (l == LL - 1) ? (LL - 1) * DD : -1;
        k_edge_csr<<<edge_blocks, 256>>>(root + (size_t)l * DD, outp, bn);
    }
}

// round 7
// speedup vs baseline: 1.9773x; 1.1621x over previous
#include <cuda_runtime.h>
#include <cuda_bf16.h>
#include <mma.h>
#include <cstdint>
#include <cstddef>

using namespace nvcuda;

// Problem constants (fixed by the reference)
#define NN 100000
#define EE 600000
#define DD 128
#define LL 5
#define BN_EPS 1e-5f
#define NT 782                 // row tiles of 128 (782*128 = 100096)
#define NPAD (NT * 128)        // padded rows so wmma stores stay in bounds
#define SROW 136               // padded smem row (bf16 elems)
#define GEMM_GRID 148

// ---------------------------------------------------------------------------
// Device scratch
// ---------------------------------------------------------------------------
__device__ __align__(16) float         g_hl[(size_t)NPAD * DD]; // post-linear (NO bias)
__device__ __align__(16) float         g_hn[(size_t)NN * DD];   // layer output (pre-BN h)
__device__ __align__(16) unsigned char g_ea[(size_t)EE * DD];   // edge_attr u8, CSR order
__device__ __align__(16) int           g_srcn[EE];              // CSR: source node per slot
__device__ __align__(16) float         g_enorm[EE];             // CSR: norm per slot
__device__ __align__(16) int           g_pos[EE];               // edge e -> CSR slot
__device__ __align__(16) int           g_degcnt[NN];
__device__ __align__(16) int           g_indeg[NN];
__device__ __align__(16) int           g_cursor[NN];
__device__ __align__(16) int           g_off[NN + 1];
__device__ __align__(16) int           g_bsum[128];
__device__ __align__(16) float         g_invdeg[NN];
__device__ __align__(16) float         g_dinv[NN];
__device__ __align__(16) float         g_scl[LL * DD];
__device__ __align__(16) float         g_sft[LL * DD];
__device__ int g_is64;

// ---------------------------------------------------------------------------
// Preprocessing
// ---------------------------------------------------------------------------
__global__ void k_detect(const int* __restrict__ ei32) {
    __shared__ int s_any;
    if (threadIdx.x == 0) s_any = 0;
    __syncthreads();
    int v = 0;
    for (int i = threadIdx.x; i < 4096; i += blockDim.x)
        v |= ei32[2 * i + 1];
    atomicOr(&s_any, v);
    __syncthreads();
    if (threadIdx.x == 0) g_is64 = (s_any == 0) ? 1 : 0;
}

__global__ void k_zero() {
    int i = blockIdx.x * blockDim.x + threadIdx.x;
    if (i < NN) { g_degcnt[i] = 0; g_indeg[i] = 0; g_cursor[i] = 0; }
}

__device__ __forceinline__ void load_edge(const void* ei, int e, int& r, int& c) {
    if (g_is64) {
        const long long* p = (const long long*)ei;
        r = (int)p[e]; c = (int)p[EE + e];
    } else {
        const int* p = (const int*)ei;
        r = p[e]; c = p[EE + e];
    }
    r = min(max(r, 0), NN - 1);
    c = min(max(c, 0), NN - 1);
}

__global__ void k_edge_pre(const void* __restrict__ ei) {
    int e = blockIdx.x * blockDim.x + threadIdx.x;
    if (e >= EE) return;
    int r, c; load_edge(ei, e, r, c);
    atomicAdd(&g_degcnt[r], 1);
    atomicAdd(&g_indeg[c], 1);
}

__global__ void k_node() {
    int n = blockIdx.x * blockDim.x + threadIdx.x;
    if (n >= NN) return;
    float d = (float)(g_degcnt[n] + 1);
    g_invdeg[n] = 1.0f / d;
    g_dinv[n]   = rsqrtf(d);
}

__global__ void k_scan1() {            // grid 98, block 1024
    __shared__ int s[1024];
    int i = blockIdx.x * 1024 + threadIdx.x;
    int v = (i < NN) ? g_indeg[i] : 0;
    s[threadIdx.x] = v;
    __syncthreads();
    for (int d = 1; d < 1024; d <<= 1) {
        int t = (threadIdx.x >= d) ? s[threadIdx.x - d] : 0;
        __syncthreads();
        s[threadIdx.x] += t;
        __syncthreads();
    }
    if (i < NN) g_off[i] = s[threadIdx.x] - v;
    if (threadIdx.x == 1023) g_bsum[blockIdx.x] = s[1023];
}

__global__ void k_scan2() {            // 1 block, 128 threads
    __shared__ int s[128];
    int t = threadIdx.x;
    s[t] = (t < 98) ? g_bsum[t] : 0;
    __syncthreads();
    for (int d = 1; d < 128; d <<= 1) {
        int v = (t >= d) ? s[t - d] : 0;
        __syncthreads();
        s[t] += v;
        __syncthreads();
    }
    if (t < 98) g_bsum[t] = s[t];
}

__global__ void k_scan3() {            // grid 98, block 1024
    int i = blockIdx.x * 1024 + threadIdx.x;
    int add = (blockIdx.x > 0) ? g_bsum[blockIdx.x - 1] : 0;
    if (i < NN) g_off[i] += add;
    if (i == NN) g_off[NN] = EE;
}

__global__ void k_place(const void* __restrict__ ei) {
    int e = blockIdx.x * blockDim.x + threadIdx.x;
    if (e >= EE) return;
    int r, c; load_edge(ei, e, r, c);
    int pos = g_off[c] + atomicAdd(&g_cursor[c], 1);
    g_srcn[pos]  = r;
    g_enorm[pos] = g_dinv[r] * g_dinv[c];
    g_pos[e]     = pos;
}

__global__ void k_pack(const int4* __restrict__ ea) {
    int i = blockIdx.x * blockDim.x + threadIdx.x;
    if (i >= EE * 32) return;
    int e = i >> 5, j = i & 31;
    int4 v = __ldg(&ea[i]);
    unsigned int u = ((unsigned)v.x & 0xffu)
                   | (((unsigned)v.y & 0xffu) << 8)
                   | (((unsigned)v.z & 0xffu) << 16)
                   | (((unsigned)v.w & 0xffu) << 24);
    ((unsigned int*)g_ea)[(size_t)g_pos[e] * 32 + j] = u;
}

__global__ void k_bnconst(const float* __restrict__ gamma, const float* __restrict__ beta,
                          const float* __restrict__ mean,  const float* __restrict__ var) {
    int i = blockIdx.x * blockDim.x + threadIdx.x;
    if (i >= LL * DD) return;
    float s = gamma[i] * rsqrtf(var[i] + BN_EPS);
    g_scl[i] = s;
    g_sft[i] = beta[i] - mean[i] * s;
}

// ---------------------------------------------------------------------------
// Tensor-core GEMM, bf16 hi/lo 3-term: g_hl = affine_relu(A) @ W^T  (NO bias)
//   W (hi/lo) resident in smem; double-buffered A tiles; 1 sync per tile;
//   persistent blocks (grid=148), each warp computes a 16x128 slice.
// ---------------------------------------------------------------------------
__global__ __launch_bounds__(256, 1)
void k_gemm_tc(const float* __restrict__ A_in, const float* __restrict__ W, int aff)
{
    extern __shared__ __nv_bfloat16 sm[];
    __nv_bfloat16* sWh = sm;                       // [128][SROW]
    __nv_bfloat16* sWl = sm + 128 * SROW;
    __nv_bfloat16* sAb = sm + 2 * 128 * SROW;      // [2 bufs][hi/lo][128][SROW]
    __shared__ float sScl[DD], sSft[DD];

    const float* A = A_in ? A_in : g_hn;
    int tid = threadIdx.x;
    bool doaff = (aff >= 0);

    if (tid < DD) {
        sScl[tid] = doaff ? g_scl[aff + tid] : 1.0f;
        sSft[tid] = doaff ? g_sft[aff + tid] : 0.0f;
    }

    // Build W hi/lo (128 rows x 32 float4)
    for (int idx = tid; idx < 128 * 32; idx += 256) {
        int row = idx >> 5, c0 = (idx & 31) << 2;
        float4 w = __ldg((const float4*)(W + row * DD + c0));
        float vs[4] = {w.x, w.y, w.z, w.w};
        #pragma unroll
        for (int j = 0; j < 4; j++) {
            __nv_bfloat16 h = __float2bfloat16(vs[j]);
            sWh[row * SROW + c0 + j] = h;
            sWl[row * SROW + c0 + j] = __float2bfloat16(vs[j] - __bfloat162float(h));
        }
    }

    int wid = tid >> 5;
    int r   = tid >> 1;            // staging row 0..127
    int ch  = (tid & 1) << 4;      // float4 col offset: 0 or 16

    int t = blockIdx.x;
    float4 st[16];
    if (t < NT) {
        int grow = min(t * 128 + r, NN - 1);
        const float4* src = (const float4*)(A + (size_t)grow * DD) + ch;
        #pragma unroll
        for (int i = 0; i < 16; i++) st[i] = __ldg(&src[i]);
    }
    __syncthreads();   // W + BN consts ready

    int buf = 0;
    while (t < NT) {
        // Convert staged tile -> sA[buf] (BN+relu applied in fp32, then split)
        __nv_bfloat16* sAh = sAb + buf * 2 * 128 * SROW;
        __nv_bfloat16* sAl = sAh + 128 * SROW;
        #pragma unroll
        for (int i = 0; i < 16; i++) {
            int c = (ch + i) * 4;
            float vs[4] = {st[i].x, st[i].y, st[i].z, st[i].w};
            #pragma unroll
            for (int j = 0; j < 4; j++) {
                float v = vs[j];
                if (doaff) v = fmaxf(fmaf(v, sScl[c + j], sSft[c + j]), 0.f);
                __nv_bfloat16 h = __float2bfloat16(v);
                sAh[r * SROW + c + j] = h;
                sAl[r * SROW + c + j] = __float2bfloat16(v - __bfloat162float(h));
            }
        }
        __syncthreads();

        // Issue next tile's global loads (overlap with MMA below)
        int tn = t + GEMM_GRID;
        if (tn < NT) {
            int grow = min(tn * 128 + r, NN - 1);
            const float4* src = (const float4*)(A + (size_t)grow * DD) + ch;
            #pragma unroll
            for (int i = 0; i < 16; i++) st[i] = __ldg(&src[i]);
        }

        // Compute: warp wid -> rows m0..m0+15, all 128 cols
        int m0 = wid * 16;
        wmma::fragment<wmma::matrix_a, 16, 16, 16, __nv_bfloat16, wmma::row_major> fah[8], fal[8];
        #pragma unroll
        for (int k = 0; k < 8; k++) {
            wmma::load_matrix_sync(fah[k], sAh + m0 * SROW + k * 16, SROW);
            wmma::load_matrix_sync(fal[k], sAl + m0 * SROW + k * 16, SROW);
        }
        float* outbase = g_hl + (size_t)(t * 128 + m0) * DD;
        #pragma unroll
        for (int nn = 0; nn < 8; nn++) {
            wmma::fragment<wmma::accumulator, 16, 16, 16, float> acc;
            wmma::fill_fragment(acc, 0.f);
            #pragma unroll
            for (int k = 0; k < 8; k++) {
                wmma::fragment<wmma::matrix_b, 16, 16, 16, __nv_bfloat16, wmma::col_major> fbh, fbl;
                wmma::load_matrix_sync(fbh, sWh + (nn * 16) * SROW + k * 16, SROW);
                wmma::load_matrix_sync(fbl, sWl + (nn * 16) * SROW + k * 16, SROW);
                wmma::mma_sync(acc, fah[k], fbh, acc);
                wmma::mma_sync(acc, fah[k], fbl, acc);
                wmma::mma_sync(acc, fal[k], fbh, acc);
            }
            wmma::store_matrix_sync(outbase + nn * 16, acc, DD, wmma::mem_row_major);
        }
        buf ^= 1;
        t = tn;
    }
}

// ---------------------------------------------------------------------------
// CSR aggregation (adds bias here): one warp per node, no atomics.
//   acc = sum_j norm_j * relu(hl[src]+bias+attr) + relu(hl[n]+bias+root)*invdeg
// ---------------------------------------------------------------------------
__device__ __forceinline__ void acc_edge(float4& acc, float4 h, unsigned int u, float nrm) {
    acc.x += fmaxf(h.x + (float)( u        & 0xffu), 0.f) * nrm;
    acc.y += fmaxf(h.y + (float)((u >>  8) & 0xffu), 0.f) * nrm;
    acc.z += fmaxf(h.z + (float)((u >> 16) & 0xffu), 0.f) * nrm;
    acc.w += fmaxf(h.w + (float)((u >> 24) & 0xffu), 0.f) * nrm;
}

__global__ __launch_bounds__(256)
void k_edge_csr(const float* __restrict__ bias, const float* __restrict__ root,
                float* __restrict__ outp, int bnoff)
{
    int warp = (blockIdx.x * blockDim.x + threadIdx.x) >> 5;
    int lane = threadIdx.x & 31;
    if (warp >= NN) return;
    int n = warp;

    int beg = __ldg(&g_off[n]);
    int end = __ldg(&g_off[n + 1]);

    const float4* hl4 = (const float4*)g_hl;
    const unsigned int* ea4 = (const unsigned int*)g_ea;
    float4 b4 = __ldg((const float4*)bias + lane);

    float4 acc = make_float4(0.f, 0.f, 0.f, 0.f);
    int j = beg;
    for (; j + 1 < end; j += 2) {
        int   s0 = __ldg(&g_srcn[j]);
        int   s1 = __ldg(&g_srcn[j + 1]);
        float n0 = __ldg(&g_enorm[j]);
        float n1 = __ldg(&g_enorm[j + 1]);
        float4 h0 = __ldg(hl4 + (size_t)s0 * 32 + lane);
        float4 h1 = __ldg(hl4 + (size_t)s1 * 32 + lane);
        unsigned int u0 = __ldg(ea4 + (size_t)j * 32 + lane);
        unsigned int u1 = __ldg(ea4 + (size_t)(j + 1) * 32 + lane);
        h0.x += b4.x; h0.y += b4.y; h0.z += b4.z; h0.w += b4.w;
        h1.x += b4.x; h1.y += b4.y; h1.z += b4.z; h1.w += b4.w;
        acc_edge(acc, h0, u0, n0);
        acc_edge(acc, h1, u1, n1);
    }
    if (j < end) {
        int   s0 = __ldg(&g_srcn[j]);
        float n0 = __ldg(&g_enorm[j]);
        float4 h0 = __ldg(hl4 + (size_t)s0 * 32 + lane);
        unsigned int u0 = __ldg(ea4 + (size_t)j * 32 + lane);
        h0.x += b4.x; h0.y += b4.y; h0.z += b4.z; h0.w += b4.w;
        acc_edge(acc, h0, u0, n0);
    }

    // self-loop: relu(hl + bias + root) * invdeg
    float4 hs = __ldg(hl4 + (size_t)n * 32 + lane);
    float4 rt = __ldg((const float4*)root + lane);
    float  id = __ldg(&g_invdeg[n]);
    acc.x += fmaxf(hs.x + b4.x + rt.x, 0.f) * id;
    acc.y += fmaxf(hs.y + b4.y + rt.y, 0.f) * id;
    acc.z += fmaxf(hs.z + b4.z + rt.z, 0.f) * id;
    acc.w += fmaxf(hs.w + b4.w + rt.w, 0.f) * id;

    if (bnoff >= 0) {   // last layer: BN (no relu) -> out
        float4 sc = *(const float4*)&g_scl[bnoff + lane * 4];
        float4 sf = *(const float4*)&g_sft[bnoff + lane * 4];
        acc.x = fmaf(acc.x, sc.x, sf.x);
        acc.y = fmaf(acc.y, sc.y, sf.y);
        acc.z = fmaf(acc.z, sc.z, sf.z);
        acc.w = fmaf(acc.w, sc.w, sf.w);
        ((float4*)outp)[(size_t)n * 32 + lane] = acc;
    } else {
        ((float4*)g_hn)[(size_t)n * 32 + lane] = acc;
    }
}

// ---------------------------------------------------------------------------
// Host driver (graph-capturable)
// ---------------------------------------------------------------------------
extern "C" void kernel_launch(void* const* d_in, const int* in_sizes, int n_in,
                              void* d_out, int out_size)
{
    const float* x     = (const float*)d_in[0];
    const void*  ei    = d_in[1];
    const int*   ea    = (const int*)d_in[2];
    const float* W     = (const float*)d_in[3];
    const float* b     = (const float*)d_in[4];
    const float* root  = (const float*)d_in[5];
    const float* gamma = (const float*)d_in[6];
    const float* beta  = (const float*)d_in[7];
    const float* mean  = (const float*)d_in[8];
    const float* var   = (const float*)d_in[9];
    (void)in_sizes; (void)n_in; (void)out_size;

    const int smem_bytes = (2 + 4) * 128 * SROW * (int)sizeof(__nv_bfloat16); // 208896
    cudaFuncSetAttribute(k_gemm_tc, cudaFuncAttributeMaxDynamicSharedMemorySize, smem_bytes);

    k_detect<<<1, 256>>>((const int*)ei);
    k_zero<<<(NN + 255) / 256, 256>>>();
    k_edge_pre<<<(EE + 255) / 256, 256>>>(ei);
    k_node<<<(NN + 255) / 256, 256>>>();
    k_scan1<<<98, 1024>>>();
    k_scan2<<<1, 128>>>();
    k_scan3<<<98, 1024>>>();
    k_place<<<(EE + 255) / 256, 256>>>(ei);
    k_pack<<<(EE * 32 + 255) / 256, 256>>>((const int4*)ea);
    k_bnconst<<<(LL * DD + 255) / 256, 256>>>(gamma, beta, mean, var);

    const int edge_blocks = (NN + 7) / 8;   // 12500

    for (int l = 0; l < LL; ++l) {
        const float* A   = (l == 0) ? x : nullptr;       // nullptr -> g_hn
        int          aff = (l == 0) ? -1 : (l - 1) * DD;
        k_gemm_tc<<<GEMM_GRID, 256, smem_bytes>>>(A, W + (size_t)l * DD * DD, aff);
        float* outp = (l == LL - 1) ? (float*)d_out : nullptr;
        int    bn   = (l == LL - 1) ? (LL - 1) * DD : -1;
        k_edge_csr<<<edge_blocks, 256>>>(b + (size_t)l * DD, root + (size_t)l * DD, outp, bn);
    }
}

// round 8
// speedup vs baseline: 2.1016x; 1.0629x over previous
#include <cuda_runtime.h>
#include <cuda_bf16.h>
#include <mma.h>
#include <cstdint>
#include <cstddef>

using namespace nvcuda;

// Problem constants (fixed by the reference)
#define NN 100000
#define EE 600000
#define DD 128
#define LL 5
#define BN_EPS 1e-5f
#define NT 782                 // row tiles of 128 (782*128 = 100096)
#define NPAD (NT * 128)        // padded rows so wmma stores stay in bounds
#define SROW 136               // padded smem row (bf16 elems)
#define GEMM_GRID 148
#define EDGE_BLOCKS 592        // 4 blocks/SM * 148 SMs, persistent warps

// ---------------------------------------------------------------------------
// Device scratch
// ---------------------------------------------------------------------------
__device__ __align__(16) float         g_hl[(size_t)NPAD * DD]; // post-linear (NO bias)
__device__ __align__(16) float         g_hn[(size_t)NN * DD];   // layer output (pre-BN h)
__device__ __align__(16) unsigned char g_ea[(size_t)EE * 32];   // edge_attr 2-bit, CSR order
__device__ __align__(16) int           g_srcn[EE];              // CSR: source node per slot
__device__ __align__(16) float         g_enorm[EE];             // CSR: norm per slot
__device__ __align__(16) int           g_pos[EE];               // edge e -> CSR slot
__device__ __align__(16) int           g_degcnt[NN];
__device__ __align__(16) int           g_indeg[NN];
__device__ __align__(16) int           g_cursor[NN];
__device__ __align__(16) int           g_off[NN + 1];
__device__ __align__(16) int           g_bsum[128];
__device__ __align__(16) float         g_invdeg[NN];
__device__ __align__(16) float         g_dinv[NN];
__device__ __align__(16) float         g_scl[LL * DD];
__device__ __align__(16) float         g_sft[LL * DD];
__device__ int g_is64;

// ---------------------------------------------------------------------------
// Preprocessing
// ---------------------------------------------------------------------------
__global__ void k_detect(const int* __restrict__ ei32) {
    __shared__ int s_any;
    if (threadIdx.x == 0) s_any = 0;
    __syncthreads();
    int v = 0;
    for (int i = threadIdx.x; i < 4096; i += blockDim.x)
        v |= ei32[2 * i + 1];
    atomicOr(&s_any, v);
    __syncthreads();
    if (threadIdx.x == 0) g_is64 = (s_any == 0) ? 1 : 0;
}

__global__ void k_zero() {
    int i = blockIdx.x * blockDim.x + threadIdx.x;
    if (i < NN) { g_degcnt[i] = 0; g_indeg[i] = 0; g_cursor[i] = 0; }
}

__device__ __forceinline__ void load_edge(const void* ei, int e, int& r, int& c) {
    if (g_is64) {
        const long long* p = (const long long*)ei;
        r = (int)p[e]; c = (int)p[EE + e];
    } else {
        const int* p = (const int*)ei;
        r = p[e]; c = p[EE + e];
    }
    r = min(max(r, 0), NN - 1);
    c = min(max(c, 0), NN - 1);
}

__global__ void k_edge_pre(const void* __restrict__ ei) {
    int e = blockIdx.x * blockDim.x + threadIdx.x;
    if (e >= EE) return;
    int r, c; load_edge(ei, e, r, c);
    atomicAdd(&g_degcnt[r], 1);
    atomicAdd(&g_indeg[c], 1);
}

__global__ void k_node() {
    int n = blockIdx.x * blockDim.x + threadIdx.x;
    if (n >= NN) return;
    float d = (float)(g_degcnt[n] + 1);
    g_invdeg[n] = 1.0f / d;
    g_dinv[n]   = rsqrtf(d);
}

__global__ void k_scan1() {            // grid 98, block 1024
    __shared__ int s[1024];
    int i = blockIdx.x * 1024 + threadIdx.x;
    int v = (i < NN) ? g_indeg[i] : 0;
    s[threadIdx.x] = v;
    __syncthreads();
    for (int d = 1; d < 1024; d <<= 1) {
        int t = (threadIdx.x >= d) ? s[threadIdx.x - d] : 0;
        __syncthreads();
        s[threadIdx.x] += t;
        __syncthreads();
    }
    if (i < NN) g_off[i] = s[threadIdx.x] - v;
    if (threadIdx.x == 1023) g_bsum[blockIdx.x] = s[1023];
}

__global__ void k_scan2() {            // 1 block, 128 threads
    __shared__ int s[128];
    int t = threadIdx.x;
    s[t] = (t < 98) ? g_bsum[t] : 0;
    __syncthreads();
    for (int d = 1; d < 128; d <<= 1) {
        int v = (t >= d) ? s[t - d] : 0;
        __syncthreads();
        s[t] += v;
        __syncthreads();
    }
    if (t < 98) g_bsum[t] = s[t];
}

__global__ void k_scan3() {            // grid 98, block 1024
    int i = blockIdx.x * 1024 + threadIdx.x;
    int add = (blockIdx.x > 0) ? g_bsum[blockIdx.x - 1] : 0;
    if (i < NN) g_off[i] += add;
    if (i == NN) g_off[NN] = EE;
}

__global__ void k_place(const void* __restrict__ ei) {
    int e = blockIdx.x * blockDim.x + threadIdx.x;
    if (e >= EE) return;
    int r, c; load_edge(ei, e, r, c);
    int pos = g_off[c] + atomicAdd(&g_cursor[c], 1);
    g_srcn[pos]  = r;
    g_enorm[pos] = g_dinv[r] * g_dinv[c];
    g_pos[e]     = pos;
}

// Pack int32 edge_attr (0..3) -> 2 bits, CSR slot order.
// Thread handles 16 features -> one u32. Edge = 32 bytes total.
// Feature f (global) lives at byte (f>>2), bits 2*(f&3) of the edge's 32B row.
__global__ void k_pack2(const int4* __restrict__ ea) {
    int i = blockIdx.x * blockDim.x + threadIdx.x;
    if (i >= EE * 8) return;
    int e = i >> 3, g = i & 7;
    const int4* p = ea + (size_t)e * 32 + g * 4;
    unsigned int u = 0;
    #pragma unroll
    for (int q = 0; q < 4; q++) {
        int4 v = __ldg(&p[q]);
        u |= ((unsigned)v.x & 3u) << (q * 8 + 0);
        u |= ((unsigned)v.y & 3u) << (q * 8 + 2);
        u |= ((unsigned)v.z & 3u) << (q * 8 + 4);
        u |= ((unsigned)v.w & 3u) << (q * 8 + 6);
    }
    ((unsigned int*)g_ea)[(size_t)g_pos[e] * 8 + g] = u;
}

__global__ void k_bnconst(const float* __restrict__ gamma, const float* __restrict__ beta,
                          const float* __restrict__ mean,  const float* __restrict__ var) {
    int i = blockIdx.x * blockDim.x + threadIdx.x;
    if (i >= LL * DD) return;
    float s = gamma[i] * rsqrtf(var[i] + BN_EPS);
    g_scl[i] = s;
    g_sft[i] = beta[i] - mean[i] * s;
}

// ---------------------------------------------------------------------------
// Tensor-core GEMM, bf16 hi/lo 3-term (unchanged from R7 WIN)
// ---------------------------------------------------------------------------
__global__ __launch_bounds__(256, 1)
void k_gemm_tc(const float* __restrict__ A_in, const float* __restrict__ W, int aff)
{
    extern __shared__ __nv_bfloat16 sm[];
    __nv_bfloat16* sWh = sm;                       // [128][SROW]
    __nv_bfloat16* sWl = sm + 128 * SROW;
    __nv_bfloat16* sAb = sm + 2 * 128 * SROW;      // [2 bufs][hi/lo][128][SROW]
    __shared__ float sScl[DD], sSft[DD];

    const float* A = A_in ? A_in : g_hn;
    int tid = threadIdx.x;
    bool doaff = (aff >= 0);

    if (tid < DD) {
        sScl[tid] = doaff ? g_scl[aff + tid] : 1.0f;
        sSft[tid] = doaff ? g_sft[aff + tid] : 0.0f;
    }

    for (int idx = tid; idx < 128 * 32; idx += 256) {
        int row = idx >> 5, c0 = (idx & 31) << 2;
        float4 w = __ldg((const float4*)(W + row * DD + c0));
        float vs[4] = {w.x, w.y, w.z, w.w};
        #pragma unroll
        for (int j = 0; j < 4; j++) {
            __nv_bfloat16 h = __float2bfloat16(vs[j]);
            sWh[row * SROW + c0 + j] = h;
            sWl[row * SROW + c0 + j] = __float2bfloat16(vs[j] - __bfloat162float(h));
        }
    }

    int wid = tid >> 5;
    int r   = tid >> 1;
    int ch  = (tid & 1) << 4;

    int t = blockIdx.x;
    float4 st[16];
    if (t < NT) {
        int grow = min(t * 128 + r, NN - 1);
        const float4* src = (const float4*)(A + (size_t)grow * DD) + ch;
        #pragma unroll
        for (int i = 0; i < 16; i++) st[i] = __ldg(&src[i]);
    }
    __syncthreads();

    int buf = 0;
    while (t < NT) {
        __nv_bfloat16* sAh = sAb + buf * 2 * 128 * SROW;
        __nv_bfloat16* sAl = sAh + 128 * SROW;
        #pragma unroll
        for (int i = 0; i < 16; i++) {
            int c = (ch + i) * 4;
            float vs[4] = {st[i].x, st[i].y, st[i].z, st[i].w};
            #pragma unroll
            for (int j = 0; j < 4; j++) {
                float v = vs[j];
                if (doaff) v = fmaxf(fmaf(v, sScl[c + j], sSft[c + j]), 0.f);
                __nv_bfloat16 h = __float2bfloat16(v);
                sAh[r * SROW + c + j] = h;
                sAl[r * SROW + c + j] = __float2bfloat16(v - __bfloat162float(h));
            }
        }
        __syncthreads();

        int tn = t + GEMM_GRID;
        if (tn < NT) {
            int grow = min(tn * 128 + r, NN - 1);
            const float4* src = (const float4*)(A + (size_t)grow * DD) + ch;
            #pragma unroll
            for (int i = 0; i < 16; i++) st[i] = __ldg(&src[i]);
        }

        int m0 = wid * 16;
        wmma::fragment<wmma::matrix_a, 16, 16, 16, __nv_bfloat16, wmma::row_major> fah[8], fal[8];
        #pragma unroll
        for (int k = 0; k < 8; k++) {
            wmma::load_matrix_sync(fah[k], sAh + m0 * SROW + k * 16, SROW);
            wmma::load_matrix_sync(fal[k], sAl + m0 * SROW + k * 16, SROW);
        }
        float* outbase = g_hl + (size_t)(t * 128 + m0) * DD;
        #pragma unroll
        for (int nn = 0; nn < 8; nn++) {
            wmma::fragment<wmma::accumulator, 16, 16, 16, float> acc;
            wmma::fill_fragment(acc, 0.f);
            #pragma unroll
            for (int k = 0; k < 8; k++) {
                wmma::fragment<wmma::matrix_b, 16, 16, 16, __nv_bfloat16, wmma::col_major> fbh, fbl;
                wmma::load_matrix_sync(fbh, sWh + (nn * 16) * SROW + k * 16, SROW);
                wmma::load_matrix_sync(fbl, sWl + (nn * 16) * SROW + k * 16, SROW);
                wmma::mma_sync(acc, fah[k], fbh, acc);
                wmma::mma_sync(acc, fah[k], fbl, acc);
                wmma::mma_sync(acc, fal[k], fbh, acc);
            }
            wmma::store_matrix_sync(outbase + nn * 16, acc, DD, wmma::mem_row_major);
        }
        buf ^= 1;
        t = tn;
    }
}

// ---------------------------------------------------------------------------
// CSR aggregation: persistent warps (~21 nodes each), 4-deep gather pipeline,
// 2-bit edge_attr (1 byte per lane per edge = one 32B sector per edge).
// ---------------------------------------------------------------------------
__device__ __forceinline__ void acc_edge2(float4& acc, float4 h, unsigned int a,
                                          float nrm, float4 b4) {
    acc.x += fmaxf(h.x + b4.x + (float)( a       & 3u), 0.f) * nrm;
    acc.y += fmaxf(h.y + b4.y + (float)((a >> 2) & 3u), 0.f) * nrm;
    acc.z += fmaxf(h.z + b4.z + (float)((a >> 4) & 3u), 0.f) * nrm;
    acc.w += fmaxf(h.w + b4.w + (float)((a >> 6) & 3u), 0.f) * nrm;
}

__global__ __launch_bounds__(256)
void k_edge_csr(const float* __restrict__ bias, const float* __restrict__ root,
                float* __restrict__ outp, int bnoff)
{
    int gw   = (blockIdx.x * blockDim.x + threadIdx.x) >> 5;
    int lane = threadIdx.x & 31;
    const int nwarps = EDGE_BLOCKS * 8;

    const float4* hl4 = (const float4*)g_hl;
    float4 b4 = __ldg((const float4*)bias + lane);
    float4 rt = __ldg((const float4*)root + lane);
    float4 sc = make_float4(0,0,0,0), sf = make_float4(0,0,0,0);
    if (bnoff >= 0) {
        sc = *(const float4*)&g_scl[bnoff + lane * 4];
        sf = *(const float4*)&g_sft[bnoff + lane * 4];
    }

    for (int n = gw; n < NN; n += nwarps) {
        int beg = __ldg(&g_off[n]);
        int end = __ldg(&g_off[n + 1]);

        float4 acc = make_float4(0.f, 0.f, 0.f, 0.f);
        int j = beg;
        for (; j + 3 < end; j += 4) {
            int   s0 = __ldg(&g_srcn[j + 0]);
            int   s1 = __ldg(&g_srcn[j + 1]);
            int   s2 = __ldg(&g_srcn[j + 2]);
            int   s3 = __ldg(&g_srcn[j + 3]);
            float n0 = __ldg(&g_enorm[j + 0]);
            float n1 = __ldg(&g_enorm[j + 1]);
            float n2 = __ldg(&g_enorm[j + 2]);
            float n3 = __ldg(&g_enorm[j + 3]);
            unsigned int a0 = __ldg(&g_ea[(size_t)(j + 0) * 32 + lane]);
            unsigned int a1 = __ldg(&g_ea[(size_t)(j + 1) * 32 + lane]);
            unsigned int a2 = __ldg(&g_ea[(size_t)(j + 2) * 32 + lane]);
            unsigned int a3 = __ldg(&g_ea[(size_t)(j + 3) * 32 + lane]);
            float4 h0 = __ldg(hl4 + (size_t)s0 * 32 + lane);
            float4 h1 = __ldg(hl4 + (size_t)s1 * 32 + lane);
            float4 h2 = __ldg(hl4 + (size_t)s2 * 32 + lane);
            float4 h3 = __ldg(hl4 + (size_t)s3 * 32 + lane);
            acc_edge2(acc, h0, a0, n0, b4);
            acc_edge2(acc, h1, a1, n1, b4);
            acc_edge2(acc, h2, a2, n2, b4);
            acc_edge2(acc, h3, a3, n3, b4);
        }
        for (; j < end; ++j) {
            int   s0 = __ldg(&g_srcn[j]);
            float n0 = __ldg(&g_enorm[j]);
            unsigned int a0 = __ldg(&g_ea[(size_t)j * 32 + lane]);
            float4 h0 = __ldg(hl4 + (size_t)s0 * 32 + lane);
            acc_edge2(acc, h0, a0, n0, b4);
        }

        // self-loop: relu(hl + bias + root) * invdeg
        float4 hs = __ldg(hl4 + (size_t)n * 32 + lane);
        float  id = __ldg(&g_invdeg[n]);
        acc.x += fmaxf(hs.x + b4.x + rt.x, 0.f) * id;
        acc.y += fmaxf(hs.y + b4.y + rt.y, 0.f) * id;
        acc.z += fmaxf(hs.z + b4.z + rt.z, 0.f) * id;
        acc.w += fmaxf(hs.w + b4.w + rt.w, 0.f) * id;

        if (bnoff >= 0) {   // last layer: BN (no relu) -> out
            acc.x = fmaf(acc.x, sc.x, sf.x);
            acc.y = fmaf(acc.y, sc.y, sf.y);
            acc.z = fmaf(acc.z, sc.z, sf.z);
            acc.w = fmaf(acc.w, sc.w, sf.w);
            ((float4*)outp)[(size_t)n * 32 + lane] = acc;
        } else {
            ((float4*)g_hn)[(size_t)n * 32 + lane] = acc;
        }
    }
}

// ---------------------------------------------------------------------------
// Host driver (graph-capturable)
// ---------------------------------------------------------------------------
extern "C" void kernel_launch(void* const* d_in, const int* in_sizes, int n_in,
                              void* d_out, int out_size)
{
    const float* x     = (const float*)d_in[0];
    const void*  ei    = d_in[1];
    const int*   ea    = (const int*)d_in[2];
    const float* W     = (const float*)d_in[3];
    const float* b     = (const float*)d_in[4];
    const float* root  = (const float*)d_in[5];
    const float* gamma = (const float*)d_in[6];
    const float* beta  = (const float*)d_in[7];
    const float* mean  = (const float*)d_in[8];
    const float* var   = (const float*)d_in[9];
    (void)in_sizes; (void)n_in; (void)out_size;

    const int smem_bytes = (2 + 4) * 128 * SROW * (int)sizeof(__nv_bfloat16); // 208896
    cudaFuncSetAttribute(k_gemm_tc, cudaFuncAttributeMaxDynamicSharedMemorySize, smem_bytes);

    k_detect<<<1, 256>>>((const int*)ei);
    k_zero<<<(NN + 255) / 256, 256>>>();
    k_edge_pre<<<(EE + 255) / 256, 256>>>(ei);
    k_node<<<(NN + 255) / 256, 256>>>();
    k_scan1<<<98, 1024>>>();
    k_scan2<<<1, 128>>>();
    k_scan3<<<98, 1024>>>();
    k_place<<<(EE + 255) / 256, 256>>>(ei);
    k_pack2<<<(EE * 8 + 255) / 256, 256>>>((const int4*)ea);
    k_bnconst<<<(LL * DD + 255) / 256, 256>>>(gamma, beta, mean, var);

    for (int l = 0; l < LL; ++l) {
        const float* A   = (l == 0) ? x : nullptr;       // nullptr -> g_hn
        int          aff = (l == 0) ? -1 : (l - 1) * DD;
        k_gemm_tc<<<GEMM_GRID, 256, smem_bytes>>>(A, W + (size_t)l * DD * DD, aff);
        float* outp = (l == LL - 1) ? (float*)d_out : nullptr;
        int    bn   = (l == LL - 1) ? (LL - 1) * DD : -1;
        k_edge_csr<<<EDGE_BLOCKS, 256>>>(b + (size_t)l * DD, root + (size_t)l * DD, outp, bn);
    }
}